// round 3
// baseline (speedup 1.0000x reference)
#include <cuda_runtime.h>
#include <cuda_bf16.h>

#define D         512
#define NTAU      100
#define HSLOTS    128          // power-of-2 circular history (write j+2 vs read j-99 => 101 apart mod 128)
#define CTAS      64
#define ROWS      8            // rows per CTA
#define THREADS   288          // 8 compute warps + 1 coordinator warp

// Persistent device state (no allocations allowed).
__device__ float g_hist[HSLOTS * D];   // circular state history, slot-contiguous
__device__ int   g_count;              // monotonic barrier counter

__global__ void reset_kernel() { g_count = 0; }

__global__ void __launch_bounds__(THREADS, 1) ndde_kernel(
    const float* __restrict__ x0,
    const float* __restrict__ tau,
    const float* __restrict__ W1,
    const float* __restrict__ W2,
    const float* __restrict__ b,
    float* __restrict__ out,
    int N)
{
    __shared__ float w1s[ROWS][D];
    __shared__ float w2s[ROWS][D];

    const int  tid   = threadIdx.x;
    const int  warp  = tid >> 5;
    const int  lane  = tid & 31;
    const bool comp  = (warp < ROWS);          // compute warp (one row each)
    const bool coord = (tid == ROWS * 32);     // coordinator: warp 8 lane 0
    const int  row   = blockIdx.x * ROWS + warp;
    const long NP1   = (long)N + 1;

    // ---- one-time: stage this CTA's rows of W1/W2 into shared memory ----
    for (int i = tid; i < ROWS * D; i += THREADS) {
        const int r = blockIdx.x * ROWS + (i >> 9);   // i / D
        const int k = i & (D - 1);
        w1s[i >> 9][k] = W1[r * D + k];
        w2s[i >> 9][k] = W2[r * D + k];
    }

    const float dt  = 0.01f * __ldg(tau);
    float b_r = 0.0f, x_r = 0.0f;
    if (comp) {
        b_r = __ldg(b + row);
        x_r = __ldg(x0 + row);
        if (lane == 0) {
            g_hist[row] = x_r;                 // slot 0 = x_0
            out[(long)row * NP1] = x_r;        // column 0
        }
    }
    __syncthreads();                            // weights staged, slot 0 published

    // acc_y0 = per-lane partial of W2[row]·x0 — constant for all steps j < NTAU
    float acc_y0 = 0.0f;
    if (comp) {
        #pragma unroll
        for (int i = 0; i < D / 32; ++i) {
            const int k = lane + 32 * i;
            acc_y0 = fmaf(w2s[warp][k], __ldg(x0 + k), acc_y0);
        }
    }
    if (coord) {
        __threadfence();                        // release slot-0 writes
        atomicAdd(&g_count, 1);
    }

    float acc_y = acc_y0;                       // per-lane partial of W2·y for the UPCOMING step j
    for (int j = 0; j < N; ++j) {
        // ---- barrier j: coordinator polls until all CTAs published x_j ----
        if (coord) {
            const int target = CTAS * (j + 1);
            while (*(volatile int*)&g_count < target) { }
            __threadfence();                    // acquire
        }
        __syncthreads();

        if (comp) {
            // ---- critical half: acc_x = W1[row]·x_j  (2 accumulators) ----
            const float* xs = &g_hist[(j & (HSLOTS - 1)) * D];
            float a0 = acc_y, a1 = 0.0f;        // both per-lane partials
            #pragma unroll
            for (int i = 0; i < D / 32; i += 2) {
                const int k  = lane + 32 * i;
                const int k2 = k + 32;
                a0 = fmaf(w1s[warp][k],  __ldcg(xs + k),  a0);
                a1 = fmaf(w1s[warp][k2], __ldcg(xs + k2), a1);
            }
            float acc = a0 + a1;
            #pragma unroll
            for (int off = 16; off; off >>= 1)
                acc += __shfl_xor_sync(0xffffffffu, acc, off);

            if (lane == 0) {
                const float z = acc + b_r;      // bias added ONCE, post-reduce
                x_r = fmaf(dt, tanhf(z), x_r);
                g_hist[((j + 1) & (HSLOTS - 1)) * D + row] = x_r;   // publish
                out[(long)row * NP1 + (j + 1)] = x_r;               // trajectory
            }
        }
        __syncthreads();
        if (coord) {
            __threadfence();                    // release x_{j+1}
            atomicAdd(&g_count, 1);             // signal barrier j+1
        }

        // ---- off-critical-path: precompute per-lane partial of W2·y for step j+1 ----
        // (y_{j+1} = x_{j+1-NTAU}, published >= 100 steps ago; overlaps with
        //  the coordinator's poll for the next barrier)
        const int jn = j + 1;
        if (comp) {
            if (jn >= NTAU) {
                const float* ys = &g_hist[((jn - NTAU) & (HSLOTS - 1)) * D];
                float y0 = 0.0f, y1 = 0.0f;
                #pragma unroll
                for (int i = 0; i < D / 32; i += 2) {
                    const int k  = lane + 32 * i;
                    const int k2 = k + 32;
                    y0 = fmaf(w2s[warp][k],  __ldcg(ys + k),  y0);
                    y1 = fmaf(w2s[warp][k2], __ldcg(ys + k2), y1);
                }
                acc_y = y0 + y1;
            } else {
                acc_y = acc_y0;
            }
        }
    }
}

extern "C" void kernel_launch(void* const* d_in, const int* in_sizes, int n_in,
                              void* d_out, int out_size) {
    const float* x0  = (const float*)d_in[0];
    const float* tau = (const float*)d_in[1];
    const float* W1  = (const float*)d_in[2];
    const float* W2  = (const float*)d_in[3];
    const float* b   = (const float*)d_in[4];
    float* out = (float*)d_out;

    const int N = out_size / D - 1;    // out is [D, N+1]

    reset_kernel<<<1, 1>>>();
    ndde_kernel<<<CTAS, THREADS>>>(x0, tau, W1, W2, b, out, N);
}